// round 8
// baseline (speedup 1.0000x reference)
#include <cuda_runtime.h>
#include <cuda_bf16.h>
#include <cstdint>

// Problem constants (fixed by the reference)
#define N_COLS  22
#define N_PAIRS 231
#define EMB     12
#define DVEC    64
#define N_PRIM  5
#define COMBO2  (EMB * EMB * 2)   // 288 floats per pair in the LUT
#define ROWSTRIDE (DVEC + 4)      // 68 floats: float4-aligned stage rows
#define GRID    128               // <= SM count (148): all blocks co-resident
#define BLK     256

// Pair index table, computed on host, passed by value (constant bank)
struct PairTab { uchar2 ij[N_PAIRS]; };

// Scratch: precomputed per-pair lookup table T[p][fi][fj][o]  (266 KB)
__device__ __align__(16) float g_T[N_PAIRS * COMBO2];

// Monotonic grid-barrier counter. NEVER reset: each replay consumes GRID
// tickets; target = (ticket/GRID + 1)*GRID. Zero-initialized at module load.
__device__ unsigned int g_bar;

// ---------------------------------------------------------------------------
// Fused persistent kernel.
//  Phase A: build LUT (pairs strided across blocks, SMEM-staged, float4 math)
//  [feats preload for this block's batch tile — overlaps others' phase A]
//  grid barrier (monotonic ticket counter, release/acquire fences)
//  Phase B: block owns one 32-row batch tile, gathers all 231 pairs,
//           direct stores (no atomics, no zero-init).
// ---------------------------------------------------------------------------
__global__ __launch_bounds__(BLK)
void fused_kernel(const int*   __restrict__ feats,
                  const float* __restrict__ tables,
                  const float* __restrict__ Wsmall,
                  const float* __restrict__ Wconcat,
                  const float* __restrict__ aw,
                  float*       __restrict__ out,
                  int B,
                  const PairTab tab)
{
    __shared__ float  sh[2][EMB * ROWSTRIDE];   // phase A staging (6.5 KB)
    __shared__ int    shf[32][N_COLS + 1];      // feats tile, stride 23
    __shared__ float2 shred[8][32];

    const int tid  = threadIdx.x;
    const int lane = tid & 31;
    const int warp = tid >> 5;

    // ---------------- Phase A: build this block's pairs ----------------
    for (int p = blockIdx.x; p < N_PAIRS; p += GRID) {
        const int i = tab.ij[p].x;
        const int j = tab.ij[p].y;

        // stage the two 12x64 embedding tables (float4, coalesced)
        const float4* __restrict__ t4 = (const float4*)tables;
        for (int e = tid; e < 2 * EMB * (DVEC / 4); e += BLK) {
            const int which = (e >= EMB * (DVEC / 4));
            const int e2  = e - which * EMB * (DVEC / 4);
            const int row = e2 >> 4, d4 = e2 & 15;
            const float4 v = __ldg(&t4[((which ? j : i) * EMB + row) * (DVEC / 4) + d4]);
            ((float4*)sh[which])[row * (ROWSTRIDE / 4) + d4] = v;
        }

        // selected primitive (arch_weights is exact one-hot of 0.0/1.0)
        int k = 0;
#pragma unroll
        for (int t = 0; t < N_PRIM; ++t)
            if (__ldg(&aw[p * N_PRIM + t]) > 0.5f) k = t;
        __syncthreads();

        for (int task = tid; task < COMBO2; task += BLK) {
            const int o     = task & 1;
            const int combo = task >> 1;
            const int fi    = combo / EMB;
            const int fj    = combo - fi * EMB;
            const float4* __restrict__ pi = (const float4*)&sh[0][fi * ROWSTRIDE];
            const float4* __restrict__ pj = (const float4*)&sh[1][fj * ROWSTRIDE];

            float acc = 0.0f;
            if (k == 4) {
                const float4* __restrict__ wa = (const float4*)(Wconcat + (p * 2 + o) * (2 * DVEC));
                const float4* __restrict__ wb = wa + (DVEC / 4);
#pragma unroll
                for (int d = 0; d < DVEC / 4; ++d) {
                    const float4 a = pi[d], b = pj[d];
                    const float4 u = __ldg(&wa[d]), v = __ldg(&wb[d]);
                    acc += u.x * a.x + u.y * a.y + u.z * a.z + u.w * a.w;
                    acc += v.x * b.x + v.y * b.y + v.z * b.z + v.w * b.w;
                }
            } else {
                const float4* __restrict__ w = (const float4*)(Wsmall + ((p * 4 + k) * 2 + o) * DVEC);
#pragma unroll
                for (int d = 0; d < DVEC / 4; ++d) {
                    const float4 a = pi[d], b = pj[d];
                    const float4 u = __ldg(&w[d]);
                    float4 z;
                    if (k == 0)      { z.x = a.x + b.x; z.y = a.y + b.y; z.z = a.z + b.z; z.w = a.w + b.w; }
                    else if (k == 1) { z.x = a.x * b.x; z.y = a.y * b.y; z.z = a.z * b.z; z.w = a.w * b.w; }
                    else if (k == 2) { z.x = fmaxf(a.x, b.x); z.y = fmaxf(a.y, b.y); z.z = fmaxf(a.z, b.z); z.w = fmaxf(a.w, b.w); }
                    else             { z.x = fminf(a.x, b.x); z.y = fminf(a.y, b.y); z.z = fminf(a.z, b.z); z.w = fminf(a.w, b.w); }
                    acc += u.x * z.x + u.y * z.y + u.z * z.z + u.w * z.w;
                }
            }
            g_T[p * COMBO2 + task] = acc;
        }
        __syncthreads();   // sh reused next iteration
    }

    // ------------- feats preload for this block's first tile -------------
    const int ntiles = (B + 31) / 32;
    if (blockIdx.x < ntiles) {
        const int bbase = blockIdx.x * 32;
        for (int e = tid; e < 32 * N_COLS; e += BLK) {
            const int row = e / N_COLS, col = e - row * N_COLS;
            const int b   = bbase + row;
            shf[row][col] = (b < B) ? feats[b * N_COLS + col] : 0;
        }
    }
    __syncthreads();

    // ---------------------- grid barrier (monotonic) ----------------------
    __threadfence();                       // release: g_T stores visible
    if (tid == 0) {
        const unsigned int ticket = atomicAdd(&g_bar, 1u);
        const unsigned int target = (ticket / GRID + 1u) * GRID;
        volatile unsigned int* bar = &g_bar;
        while (*bar < target) { }
        __threadfence();                   // acquire
    }
    __syncthreads();

    // ---------------- Phase B: gather + reduce + direct store -------------
    for (int tile = blockIdx.x; tile < ntiles; tile += GRID) {
        if (tile != (int)blockIdx.x) {     // reload feats for extra tiles (B > 4096)
            __syncthreads();
            const int bbase = tile * 32;
            for (int e = tid; e < 32 * N_COLS; e += BLK) {
                const int row = e / N_COLS, col = e - row * N_COLS;
                const int b   = bbase + row;
                shf[row][col] = (b < B) ? feats[b * N_COLS + col] : 0;
            }
            __syncthreads();
        }

        const float2* __restrict__ T2 = (const float2*)g_T;
        float ax = 0.0f, ay = 0.0f;

        // warp w handles pairs w, w+8, ... (29 independent gathers, L1-coherent:
        // all 32 lanes hit one pair's 1.15 KB LUT region)
#pragma unroll 8
        for (int p = warp; p < N_PAIRS; p += 8) {
            const uchar2 ij = tab.ij[p];            // constant bank, uniform
            const int fi = shf[lane][ij.x];
            const int fj = shf[lane][ij.y];
            const float2 v = __ldg(&T2[p * (EMB * EMB) + fi * EMB + fj]);
            ax += v.x;
            ay += v.y;
        }

        shred[warp][lane] = make_float2(ax, ay);
        __syncthreads();

        if (warp == 0) {
            float sx = 0.0f, sy = 0.0f;
#pragma unroll
            for (int w = 0; w < 8; ++w) {
                const float2 s = shred[w][lane];
                sx += s.x;
                sy += s.y;
            }
            const int b = tile * 32 + lane;
            if (b < B) ((float2*)out)[b] = make_float2(sx, sy);
        }
    }
}

// ---------------------------------------------------------------------------
// Launch: ONE persistent kernel, graph-safe (single launch node).
// Inputs (metadata order): feats(i32), tables(f32), W_small(f32),
//                          W_concat(f32), arch_weights(f32)
// ---------------------------------------------------------------------------
extern "C" void kernel_launch(void* const* d_in, const int* in_sizes, int n_in,
                              void* d_out, int out_size)
{
    const int*   feats   = (const int*)  d_in[0];
    const float* tables  = (const float*)d_in[1];
    const float* Wsmall  = (const float*)d_in[2];
    const float* Wconcat = (const float*)d_in[3];
    const float* aw      = (const float*)d_in[4];
    float*       out     = (float*)d_out;

    const int B = in_sizes[0] / N_COLS;   // 4096

    // host-side triu(N_COLS, 1) pair table -> constant-bank kernel param
    PairTab tab;
    {
        int p = 0;
        for (int i = 0; i < N_COLS; ++i)
            for (int j = i + 1; j < N_COLS; ++j, ++p)
                tab.ij[p] = make_uchar2((unsigned char)i, (unsigned char)j);
    }

    fused_kernel<<<GRID, BLK>>>(feats, tables, Wsmall, Wconcat, aw, out, B, tab);
}

// round 9
// speedup vs baseline: 1.5052x; 1.5052x over previous
#include <cuda_runtime.h>
#include <cuda_bf16.h>
#include <cstdint>

// Problem constants (fixed by the reference)
#define N_COLS  22
#define N_PAIRS 231
#define EMB     12
#define DVEC    64
#define N_PRIM  5
#define COMBO2  (EMB * EMB * 2)   // 288 floats per pair in the LUT
#define NCHUNK  8                 // pair-dimension split for kernel 2
#define CHUNKSZ ((N_PAIRS + NCHUNK - 1) / NCHUNK)   // 29

// Pair index table, computed on host, passed by value (constant bank)
struct PairTab { uchar2 ij[N_PAIRS]; };

// Scratch: precomputed per-pair lookup table T[p][fi][fj][o]  (266 KB)
__device__ __align__(16) float g_T[N_PAIRS * COMBO2];

// ---------------------------------------------------------------------------
// Kernel 1: warp-per-(p, fi). No SMEM, no __syncthreads, no staging.
// 16-lane halves: lane hl holds dims 4hl..4hl+3 (float4). Half h computes
// fj = 2t+h for t=0..5. All loads are coalesced LDG.128 from L2-hot tables.
// Shuffle-reduce (xor 8,4,2,1) stays inside each 16-lane half.
// Also zero-initializes out[] (first 32 blocks cover 8192 floats).
// ---------------------------------------------------------------------------
__global__ __launch_bounds__(256)
void build_lut_kernel(const float* __restrict__ tables,
                      const float* __restrict__ Wsmall,
                      const float* __restrict__ Wconcat,
                      const float* __restrict__ aw,
                      float* __restrict__ out, int outN,
                      const PairTab tab)
{
    // zero the output buffer (poisoned by harness)
    {
        const int gz = blockIdx.x * 256 + threadIdx.x;
        if (gz < outN) out[gz] = 0.0f;
    }

    const int gwarp = (blockIdx.x * 256 + threadIdx.x) >> 5;
    if (gwarp >= N_PAIRS * EMB) return;

    const int p    = gwarp / EMB;
    const int fi   = gwarp - p * EMB;
    const int lane = threadIdx.x & 31;
    const int half = lane >> 4;          // 0 or 1
    const int hl   = lane & 15;          // lane within half

    const int i = tab.ij[p].x;
    const int j = tab.ij[p].y;

    // selected primitive (arch_weights is exact one-hot of 0.0/1.0); warp-uniform
    int k = 0;
#pragma unroll
    for (int t = 0; t < N_PRIM; ++t)
        if (__ldg(&aw[p * N_PRIM + t]) > 0.5f) k = t;

    const float4* __restrict__ t4 = (const float4*)tables;
    const float4 Pi = __ldg(&t4[(i * EMB + fi) * (DVEC / 4) + hl]);

    float4 w0, w1;          // weights over this lane's 4 dims, o = 0 / 1
    float  pp0 = 0.0f, pp1 = 0.0f;   // reduced P-part for concat
    if (k == 4) {
        const float4* __restrict__ wc = (const float4*)(Wconcat + p * 2 * (2 * DVEC));
        const float4 a0 = __ldg(&wc[hl]);            // o=0, P dims
        const float4 a1 = __ldg(&wc[32 + hl]);       // o=1, P dims
        w0 = __ldg(&wc[16 + hl]);                    // o=0, Q dims
        w1 = __ldg(&wc[48 + hl]);                    // o=1, Q dims
        pp0 = a0.x * Pi.x + a0.y * Pi.y + a0.z * Pi.z + a0.w * Pi.w;
        pp1 = a1.x * Pi.x + a1.y * Pi.y + a1.z * Pi.z + a1.w * Pi.w;
#pragma unroll
        for (int off = 8; off; off >>= 1) {
            pp0 += __shfl_xor_sync(0xffffffffu, pp0, off);
            pp1 += __shfl_xor_sync(0xffffffffu, pp1, off);
        }
    } else {
        const float4* __restrict__ ws = (const float4*)(Wsmall + (p * 4 + k) * 2 * DVEC);
        w0 = __ldg(&ws[hl]);
        w1 = __ldg(&ws[16 + hl]);
    }

    float2* __restrict__ T2 = (float2*)g_T;

#pragma unroll
    for (int t = 0; t < 6; ++t) {
        const int fj = t * 2 + half;
        const float4 Q = __ldg(&t4[(j * EMB + fj) * (DVEC / 4) + hl]);

        float4 z;
        if (k == 0)      { z.x = Pi.x + Q.x; z.y = Pi.y + Q.y; z.z = Pi.z + Q.z; z.w = Pi.w + Q.w; }
        else if (k == 1) { z.x = Pi.x * Q.x; z.y = Pi.y * Q.y; z.z = Pi.z * Q.z; z.w = Pi.w * Q.w; }
        else if (k == 2) { z.x = fmaxf(Pi.x, Q.x); z.y = fmaxf(Pi.y, Q.y); z.z = fmaxf(Pi.z, Q.z); z.w = fmaxf(Pi.w, Q.w); }
        else if (k == 3) { z.x = fminf(Pi.x, Q.x); z.y = fminf(Pi.y, Q.y); z.z = fminf(Pi.z, Q.z); z.w = fminf(Pi.w, Q.w); }
        else             { z = Q; }   // concat: Q-part only; P-part already reduced

        float s0 = z.x * w0.x + z.y * w0.y + z.z * w0.z + z.w * w0.w;
        float s1 = z.x * w1.x + z.y * w1.y + z.z * w1.z + z.w * w1.w;
#pragma unroll
        for (int off = 8; off; off >>= 1) {
            s0 += __shfl_xor_sync(0xffffffffu, s0, off);
            s1 += __shfl_xor_sync(0xffffffffu, s1, off);
        }
        if (k == 4) { s0 += pp0; s1 += pp1; }

        if (hl == 0)
            T2[p * (EMB * EMB) + fi * EMB + fj] = make_float2(s0, s1);
    }
}

// ---------------------------------------------------------------------------
// Kernel 2: out[b, :] += sum_{p in chunk} T[p, f[i_p], f[j_p], :]
// grid = (B/32) x 8 chunks = 1024 blocks -> occupancy ~80%. lane = batch
// element; warp w strides its chunk's 29 pairs (<=4 independent unrolled
// gathers). All 32 lanes gather inside ONE pair's 1.15 KB LUT region.
// Cross-warp SMEM reduce, then atomicAdd (out zeroed by kernel 1).
// ---------------------------------------------------------------------------
__global__ __launch_bounds__(256)
void accumulate_kernel(const int* __restrict__ feats,
                       float* __restrict__ out,
                       int B,
                       const PairTab tab)
{
    __shared__ int    shf[32][N_COLS + 1];   // stride 23: coprime with 32 banks
    __shared__ float2 shred[8][32];

    const int tid   = threadIdx.x;
    const int lane  = tid & 31;
    const int warp  = tid >> 5;
    const int bbase = blockIdx.x * 32;
    const int p0    = blockIdx.y * CHUNKSZ;
    const int npair = min(N_PAIRS - p0, CHUNKSZ);

    // coalesced, cooperative load of this block's 32 feats rows
    for (int e = tid; e < 32 * N_COLS; e += 256) {
        const int row = e / N_COLS, col = e - row * N_COLS;
        const int b   = bbase + row;
        shf[row][col] = (b < B) ? feats[b * N_COLS + col] : 0;
    }
    __syncthreads();

    const float2* __restrict__ T2 = (const float2*)g_T;
    float ax = 0.0f, ay = 0.0f;

    // warp w handles chunk-local pairs w, w+8, ... (<= 4 independent gathers)
#pragma unroll 4
    for (int t = warp; t < npair; t += 8) {
        const uchar2 ij = tab.ij[p0 + t];        // constant bank, uniform
        const int fi = shf[lane][ij.x];
        const int fj = shf[lane][ij.y];
        const float2 v = __ldg(&T2[(p0 + t) * (EMB * EMB) + fi * EMB + fj]);
        ax += v.x;
        ay += v.y;
    }

    shred[warp][lane] = make_float2(ax, ay);
    __syncthreads();

    if (warp == 0) {
        float sx = 0.0f, sy = 0.0f;
#pragma unroll
        for (int w = 0; w < 8; ++w) {
            const float2 s = shred[w][lane];
            sx += s.x;
            sy += s.y;
        }
        const int b = bbase + lane;
        if (b < B) {
            atomicAdd(&out[b * 2 + 0], sx);
            atomicAdd(&out[b * 2 + 1], sy);
        }
    }
}

// ---------------------------------------------------------------------------
// Launch: two kernels on the default stream (implicit ordering), graph-safe.
// Inputs (metadata order): feats(i32), tables(f32), W_small(f32),
//                          W_concat(f32), arch_weights(f32)
// ---------------------------------------------------------------------------
extern "C" void kernel_launch(void* const* d_in, const int* in_sizes, int n_in,
                              void* d_out, int out_size)
{
    const int*   feats   = (const int*)  d_in[0];
    const float* tables  = (const float*)d_in[1];
    const float* Wsmall  = (const float*)d_in[2];
    const float* Wconcat = (const float*)d_in[3];
    const float* aw      = (const float*)d_in[4];
    float*       out     = (float*)d_out;

    const int B = in_sizes[0] / N_COLS;   // 4096

    // host-side triu(N_COLS, 1) pair table -> constant-bank kernel param
    PairTab tab;
    {
        int p = 0;
        for (int i = 0; i < N_COLS; ++i)
            for (int j = i + 1; j < N_COLS; ++j, ++p)
                tab.ij[p] = make_uchar2((unsigned char)i, (unsigned char)j);
    }

    const int k1_blocks = (N_PAIRS * EMB * 32 + 255) / 256;   // 347
    build_lut_kernel<<<k1_blocks, 256>>>(tables, Wsmall, Wconcat, aw,
                                         out, out_size, tab);

    dim3 grid((B + 31) / 32, NCHUNK);     // 128 x 8 = 1024 blocks
    accumulate_kernel<<<grid, 256>>>(feats, out, B, tab);
}